// round 3
// baseline (speedup 1.0000x reference)
#include <cuda_runtime.h>
#include <cuda_fp16.h>
#include <cstdint>
#include <cstddef>

// ============================ problem dims ============================
#define MDIM 8192
#define NDIM 4096
#define KDIM 4096

// ============================ scratch (no allocs allowed) =============
__device__ __half g_Xh[(size_t)MDIM * KDIM];   // 67 MB fp16 activations
__device__ __half g_Wh[(size_t)NDIM * KDIM];   // 34 MB fp16 ternary weights
__device__ double g_part[2048];
__device__ float  g_gamma;

// ============================ PTX helpers =============================
__device__ __forceinline__ uint32_t s2u(const void* p) {
    uint32_t a;
    asm("{ .reg .u64 t; cvta.to.shared.u64 t, %1; cvt.u32.u64 %0, t; }"
        : "=r"(a) : "l"(p));
    return a;
}

#define CP16(dst, src) \
    asm volatile("cp.async.cg.shared.global [%0], [%1], 16;" :: "r"(dst), "l"(src))
#define CP_COMMIT() asm volatile("cp.async.commit_group;" ::: "memory")
#define CP_WAIT(n)  asm volatile("cp.async.wait_group %0;" :: "n"(n) : "memory")

#define LDSM_X4(r0, r1, r2, r3, addr) \
    asm volatile("ldmatrix.sync.aligned.m8n8.x4.shared.b16 {%0,%1,%2,%3}, [%4];" \
                 : "=r"(r0), "=r"(r1), "=r"(r2), "=r"(r3) : "r"(addr))

#define MMA16816(c, a, b) \
    asm volatile("mma.sync.aligned.m16n8k16.row.col.f32.f16.f16.f32 " \
                 "{%0,%1,%2,%3}, {%4,%5,%6,%7}, {%8,%9}, {%0,%1,%2,%3};" \
                 : "+f"((c)[0]), "+f"((c)[1]), "+f"((c)[2]), "+f"((c)[3]) \
                 : "r"((a)[0]), "r"((a)[1]), "r"((a)[2]), "r"((a)[3]), \
                   "r"((b)[0]), "r"((b)[1]))

// ============================ prepass kernels =========================
// 1) sum |w| (deterministic two-pass, double accumulation)
__global__ void absum_kernel(const float* __restrict__ w) {
    __shared__ double sh[256];
    int tid = threadIdx.x;
    size_t idx = (size_t)blockIdx.x * 256 + tid;
    double s = 0.0;
    #pragma unroll 4
    for (int i = 0; i < 32; i++)
        s += (double)fabsf(w[idx + (size_t)i * 524288]);
    sh[tid] = s; __syncthreads();
    for (int off = 128; off; off >>= 1) {
        if (tid < off) sh[tid] += sh[tid + off];
        __syncthreads();
    }
    if (tid == 0) g_part[blockIdx.x] = sh[0];
}

__global__ void gamma_kernel() {
    __shared__ double sh[256];
    int tid = threadIdx.x;
    double s = 0.0;
    for (int i = 0; i < 8; i++) s += g_part[tid * 8 + i];
    sh[tid] = s; __syncthreads();
    for (int off = 128; off; off >>= 1) {
        if (tid < off) sh[tid] += sh[tid + off];
        __syncthreads();
    }
    if (tid == 0) {
        float gm = (float)(sh[0] / 16777216.0);
        g_gamma = fmaxf(gm, 1e-8f);
    }
}

// 2+3 merged: blocks [0,8192) ternary-quantize W -> fp16; rest convert X -> fp16.
__global__ void quantconv_kernel(const float* __restrict__ w,
                                 const float* __restrict__ x) {
    size_t bid = blockIdx.x;
    if (bid < 8192) {
        float g = g_gamma;
        size_t base = (bid * 256 + threadIdx.x) * 8;
        float4 a = *(const float4*)(w + base);
        float4 b = *(const float4*)(w + base + 4);
        float v[8] = {a.x, a.y, a.z, a.w, b.x, b.y, b.z, b.w};
        __half h[8];
        #pragma unroll
        for (int i = 0; i < 8; i++) {
            float q = rintf(__fdiv_rn(v[i], g));   // round-half-even, IEEE div
            q = fminf(fmaxf(q, -1.0f), 1.0f);
            h[i] = __float2half_rn(q);
        }
        *(uint4*)(&g_Wh[base]) = *(const uint4*)h;
    } else {
        size_t base = ((bid - 8192) * 256 + threadIdx.x) * 8;
        float4 a = *(const float4*)(x + base);
        float4 b = *(const float4*)(x + base + 4);
        __half h[8] = {__float2half_rn(a.x), __float2half_rn(a.y),
                       __float2half_rn(a.z), __float2half_rn(a.w),
                       __float2half_rn(b.x), __float2half_rn(b.y),
                       __float2half_rn(b.z), __float2half_rn(b.w)};
        *(uint4*)(&g_Xh[base]) = *(const uint4*)h;
    }
}

// ============================ GEMM kernel =============================
// CTA tile 256(M) x 128(N), 256 threads = 8 warps (4x2), warp tile 64x64.
// K staged in 64-half (128B/row) chunks, 4-stage cp.async pipeline.
// Swizzle: 16B chunk index ^= (row & 7) -> conflict-free ldmatrix + stores.
#define BM 256
#define BN 128
#define KSTEP 64
#define NK (KDIM / KSTEP)                 // 64
#define STAGES 4
#define A_BYTES (BM * 128)                // 32 KB
#define B_BYTES (BN * 128)                // 16 KB
#define STG_BYTES (A_BYTES + B_BYTES)     // 48 KB
#define SMEM_TOTAL (STAGES * STG_BYTES)   // 192 KB

__global__ void __launch_bounds__(256, 1)
gemm_kernel(float* __restrict__ out, const float* __restrict__ bias) {
    extern __shared__ char smem[];
    uint32_t sb = s2u(smem);
    int tid = threadIdx.x, wid = tid >> 5, lid = tid & 31;
    int m0 = blockIdx.x * BM;
    int n0 = blockIdx.y * BN;
    int wm = (wid >> 1) * 64;             // warp M offset (4 rows of warps)
    int wn = (wid & 1) * 64;              // warp N offset (2 cols of warps)

    // A frag x4: lanes 0-15 -> 16 rows, k-chunk sel by lane>>4
    int a_row = wm + (lid & 15);
    int a_ks  = lid >> 4;
    // B frag x4: lanes {0-7,8-15,16-23,24-31} -> (n0-7,k0),(n0-7,k8),(n8-15,k0),(n8-15,k8)
    int b_row = wn + ((lid >> 4) << 3) + (lid & 7);
    int b_ks  = (lid >> 3) & 1;

    float acc[4][8][4];
    #pragma unroll
    for (int i = 0; i < 4; i++)
        #pragma unroll
        for (int j = 0; j < 8; j++)
            #pragma unroll
            for (int r = 0; r < 4; r++) acc[i][j][r] = 0.0f;

    auto load_stage = [&](int buf, int kt) {
        int k0 = kt * KSTEP;
        uint32_t sA = sb + buf * STG_BYTES;
        uint32_t sB = sA + A_BYTES;
        #pragma unroll
        for (int i = 0; i < 8; i++) {              // A: 256 rows x 8 chunks
            int cid = tid + i * 256;
            int row = cid >> 3, ch = cid & 7;
            const __half* src = &g_Xh[(size_t)(m0 + row) * KDIM + k0 + ch * 8];
            CP16(sA + row * 128 + ((ch ^ (row & 7)) << 4), src);
        }
        #pragma unroll
        for (int i = 0; i < 4; i++) {              // B: 128 rows x 8 chunks
            int cid = tid + i * 256;
            int row = cid >> 3, ch = cid & 7;
            const __half* src = &g_Wh[(size_t)(n0 + row) * KDIM + k0 + ch * 8];
            CP16(sB + row * 128 + ((ch ^ (row & 7)) << 4), src);
        }
    };

    #pragma unroll
    for (int s = 0; s < STAGES - 1; s++) { load_stage(s, s); CP_COMMIT(); }

    #pragma unroll 1
    for (int kt = 0; kt < NK; kt++) {
        CP_WAIT(STAGES - 2);
        __syncthreads();

        int nk = kt + STAGES - 1;
        if (nk < NK) load_stage(nk & (STAGES - 1), nk);
        CP_COMMIT();

        uint32_t sA = sb + (kt & (STAGES - 1)) * STG_BYTES;
        uint32_t sB = sA + A_BYTES;

        #pragma unroll
        for (int kk = 0; kk < 4; kk++) {
            uint32_t af[4][4], bf[4][4];
            #pragma unroll
            for (int mi = 0; mi < 4; mi++) {
                int m = a_row + mi * 16;
                int kch = kk * 2 + a_ks;
                uint32_t ad = sA + m * 128 + ((kch ^ (m & 7)) << 4);
                LDSM_X4(af[mi][0], af[mi][1], af[mi][2], af[mi][3], ad);
            }
            #pragma unroll
            for (int ni = 0; ni < 4; ni++) {
                int n = b_row + ni * 16;
                int kch = kk * 2 + b_ks;
                uint32_t bd = sB + n * 128 + ((kch ^ (n & 7)) << 4);
                LDSM_X4(bf[ni][0], bf[ni][1], bf[ni][2], bf[ni][3], bd);
            }
            #pragma unroll
            for (int mi = 0; mi < 4; mi++)
                #pragma unroll
                for (int nj = 0; nj < 8; nj++) {
                    uint32_t bb[2] = {bf[nj >> 1][(nj & 1) * 2],
                                      bf[nj >> 1][(nj & 1) * 2 + 1]};
                    MMA16816(acc[mi][nj], af[mi], bb);
                }
        }
    }

    // ---- epilogue: direct reg -> global with bias ----
    #pragma unroll
    for (int nj = 0; nj < 8; nj++) {
        int n = n0 + wn + nj * 8 + (lid & 3) * 2;
        float2 bv = *(const float2*)(bias + n);
        #pragma unroll
        for (int mi = 0; mi < 4; mi++) {
            int m = m0 + wm + mi * 16 + (lid >> 2);
            float2 v0 = {acc[mi][nj][0] + bv.x, acc[mi][nj][1] + bv.y};
            float2 v1 = {acc[mi][nj][2] + bv.x, acc[mi][nj][3] + bv.y};
            *(float2*)(out + (size_t)m * NDIM + n) = v0;
            *(float2*)(out + (size_t)(m + 8) * NDIM + n) = v1;
        }
    }
}

// ============================ launch ==================================
extern "C" void kernel_launch(void* const* d_in, const int* in_sizes, int n_in,
                              void* d_out, int out_size) {
    const float* x    = (const float*)d_in[0];
    const float* w    = (const float*)d_in[1];
    const float* bias = (const float*)d_in[2];
    float* out = (float*)d_out;

    absum_kernel<<<2048, 256>>>(w);
    gamma_kernel<<<1, 256>>>();
    quantconv_kernel<<<24576, 256>>>(w, x);

    cudaFuncSetAttribute(gemm_kernel, cudaFuncAttributeMaxDynamicSharedMemorySize,
                         SMEM_TOTAL);
    gemm_kernel<<<dim3(MDIM / BM, NDIM / BN), 256, SMEM_TOTAL>>>(out, bias);
}

// round 4
// speedup vs baseline: 1.0266x; 1.0266x over previous
#include <cuda_runtime.h>
#include <cuda_fp16.h>
#include <cstdint>
#include <cstddef>

// ============================ problem dims ============================
#define MDIM 8192
#define NDIM 4096
#define KDIM 4096

// ============================ scratch (no allocs allowed) =============
__device__ __half g_Xh[(size_t)MDIM * KDIM];   // 67 MB fp16 activations
__device__ __half g_Wh[(size_t)NDIM * KDIM];   // 34 MB fp16 ternary weights
__device__ double g_part[2048];
__device__ float  g_gamma;

// ============================ PTX helpers =============================
__device__ __forceinline__ uint32_t s2u(const void* p) {
    uint32_t a;
    asm("{ .reg .u64 t; cvta.to.shared.u64 t, %1; cvt.u32.u64 %0, t; }"
        : "=r"(a) : "l"(p));
    return a;
}

#define CP16(dst, src) \
    asm volatile("cp.async.cg.shared.global [%0], [%1], 16;" :: "r"(dst), "l"(src))
#define CP_COMMIT() asm volatile("cp.async.commit_group;" ::: "memory")
#define CP_WAIT(n)  asm volatile("cp.async.wait_group %0;" :: "n"(n) : "memory")

#define LDSM_X4(r0, r1, r2, r3, addr) \
    asm volatile("ldmatrix.sync.aligned.m8n8.x4.shared.b16 {%0,%1,%2,%3}, [%4];" \
                 : "=r"(r0), "=r"(r1), "=r"(r2), "=r"(r3) : "r"(addr))

#define MMA16816(c, a, b) \
    asm volatile("mma.sync.aligned.m16n8k16.row.col.f32.f16.f16.f32 " \
                 "{%0,%1,%2,%3}, {%4,%5,%6,%7}, {%8,%9}, {%0,%1,%2,%3};" \
                 : "+f"((c)[0]), "+f"((c)[1]), "+f"((c)[2]), "+f"((c)[3]) \
                 : "r"((a)[0]), "r"((a)[1]), "r"((a)[2]), "r"((a)[3]), \
                   "r"((b)[0]), "r"((b)[1]))

// ============================ prepass kernels =========================
__global__ void absum_kernel(const float* __restrict__ w) {
    __shared__ double sh[256];
    int tid = threadIdx.x;
    size_t idx = (size_t)blockIdx.x * 256 + tid;
    double s = 0.0;
    #pragma unroll 4
    for (int i = 0; i < 32; i++)
        s += (double)fabsf(w[idx + (size_t)i * 524288]);
    sh[tid] = s; __syncthreads();
    for (int off = 128; off; off >>= 1) {
        if (tid < off) sh[tid] += sh[tid + off];
        __syncthreads();
    }
    if (tid == 0) g_part[blockIdx.x] = sh[0];
}

__global__ void gamma_kernel() {
    __shared__ double sh[256];
    int tid = threadIdx.x;
    double s = 0.0;
    for (int i = 0; i < 8; i++) s += g_part[tid * 8 + i];
    sh[tid] = s; __syncthreads();
    for (int off = 128; off; off >>= 1) {
        if (tid < off) sh[tid] += sh[tid + off];
        __syncthreads();
    }
    if (tid == 0) {
        float gm = (float)(sh[0] / 16777216.0);
        g_gamma = fmaxf(gm, 1e-8f);
    }
}

// merged: blocks [0,8192) ternary-quantize W -> fp16; rest convert X -> fp16.
__global__ void quantconv_kernel(const float* __restrict__ w,
                                 const float* __restrict__ x) {
    size_t bid = blockIdx.x;
    if (bid < 8192) {
        float g = g_gamma;
        size_t base = (bid * 256 + threadIdx.x) * 8;
        float4 a = *(const float4*)(w + base);
        float4 b = *(const float4*)(w + base + 4);
        float v[8] = {a.x, a.y, a.z, a.w, b.x, b.y, b.z, b.w};
        __half h[8];
        #pragma unroll
        for (int i = 0; i < 8; i++) {
            float q = rintf(__fdiv_rn(v[i], g));   // round-half-even, IEEE div
            q = fminf(fmaxf(q, -1.0f), 1.0f);
            h[i] = __float2half_rn(q);
        }
        *(uint4*)(&g_Wh[base]) = *(const uint4*)h;
    } else {
        size_t base = ((bid - 8192) * 256 + threadIdx.x) * 8;
        float4 a = *(const float4*)(x + base);
        float4 b = *(const float4*)(x + base + 4);
        __half h[8] = {__float2half_rn(a.x), __float2half_rn(a.y),
                       __float2half_rn(a.z), __float2half_rn(a.w),
                       __float2half_rn(b.x), __float2half_rn(b.y),
                       __float2half_rn(b.z), __float2half_rn(b.w)};
        *(uint4*)(&g_Xh[base]) = *(const uint4*)h;
    }
}

// ============================ GEMM kernel =============================
// CTA 256(M) x 128(N), 256 thr = 8 warps (4x2), warp tile 64x64.
// 4-stage cp.async pipeline, KSTEP=64. Frag double-buffer across kk.
#define BM 256
#define BN 128
#define KSTEP 64
#define NK (KDIM / KSTEP)                 // 64
#define STAGES 4
#define A_BYTES (BM * 128)                // 32 KB
#define B_BYTES (BN * 128)                // 16 KB
#define STG_BYTES (A_BYTES + B_BYTES)     // 48 KB
#define SMEM_TOTAL (STAGES * STG_BYTES)   // 192 KB

__global__ void __launch_bounds__(256, 1)
gemm_kernel(float* __restrict__ out, const float* __restrict__ bias) {
    extern __shared__ char smem[];
    uint32_t sb = s2u(smem);
    int tid = threadIdx.x, wid = tid >> 5, lid = tid & 31;
    int m0 = blockIdx.x * BM;
    int n0 = blockIdx.y * BN;
    int wm = (wid >> 1) * 64;
    int wn = (wid & 1) * 64;

    int a_row = wm + (lid & 15);
    int a_ks  = lid >> 4;
    int b_row = wn + ((lid >> 4) << 3) + (lid & 7);
    int b_ks  = (lid >> 3) & 1;

    float acc[4][8][4];
    #pragma unroll
    for (int i = 0; i < 4; i++)
        #pragma unroll
        for (int j = 0; j < 8; j++)
            #pragma unroll
            for (int r = 0; r < 4; r++) acc[i][j][r] = 0.0f;

    auto load_stage = [&](int buf, int kt) {
        int k0 = kt * KSTEP;
        uint32_t sA = sb + buf * STG_BYTES;
        uint32_t sB = sA + A_BYTES;
        #pragma unroll
        for (int i = 0; i < 8; i++) {              // A: 256 rows x 8 chunks
            int cid = tid + i * 256;
            int row = cid >> 3, ch = cid & 7;
            const __half* src = &g_Xh[(size_t)(m0 + row) * KDIM + k0 + ch * 8];
            CP16(sA + row * 128 + ((ch ^ (row & 7)) << 4), src);
        }
        #pragma unroll
        for (int i = 0; i < 4; i++) {              // B: 128 rows x 8 chunks
            int cid = tid + i * 256;
            int row = cid >> 3, ch = cid & 7;
            const __half* src = &g_Wh[(size_t)(n0 + row) * KDIM + k0 + ch * 8];
            CP16(sB + row * 128 + ((ch ^ (row & 7)) << 4), src);
        }
    };

    auto ldfrags = [&](int kchb, uint32_t sA, uint32_t sB,
                       uint32_t (&af)[4][4], uint32_t (&bf)[4][4]) {
        #pragma unroll
        for (int mi = 0; mi < 4; mi++) {
            int m = a_row + mi * 16;
            int kch = kchb + a_ks;
            uint32_t ad = sA + m * 128 + ((kch ^ (m & 7)) << 4);
            LDSM_X4(af[mi][0], af[mi][1], af[mi][2], af[mi][3], ad);
        }
        #pragma unroll
        for (int ni = 0; ni < 4; ni++) {
            int n = b_row + ni * 16;
            int kch = kchb + b_ks;
            uint32_t bd = sB + n * 128 + ((kch ^ (n & 7)) << 4);
            LDSM_X4(bf[ni][0], bf[ni][1], bf[ni][2], bf[ni][3], bd);
        }
    };

    #pragma unroll
    for (int s = 0; s < STAGES - 1; s++) { load_stage(s, s); CP_COMMIT(); }

    uint32_t af[2][4][4], bf[2][4][4];

    #pragma unroll 1
    for (int kt = 0; kt < NK; kt++) {
        CP_WAIT(STAGES - 2);
        __syncthreads();

        uint32_t sA = sb + (kt & (STAGES - 1)) * STG_BYTES;
        uint32_t sB = sA + A_BYTES;

        // start the math dependency chain first...
        ldfrags(0, sA, sB, af[0], bf[0]);

        // ...then issue next stage's cp.asyncs (their issue cost overlaps HMMAs)
        int nk = kt + STAGES - 1;
        if (nk < NK) load_stage(nk & (STAGES - 1), nk);
        CP_COMMIT();

        #pragma unroll
        for (int kk = 0; kk < 4; kk++) {
            int cur = kk & 1;
            if (kk < 3)
                ldfrags((kk + 1) * 2, sA, sB, af[cur ^ 1], bf[cur ^ 1]);
            #pragma unroll
            for (int mi = 0; mi < 4; mi++)
                #pragma unroll
                for (int nj = 0; nj < 8; nj++) {
                    uint32_t bb[2] = {bf[cur][nj >> 1][(nj & 1) * 2],
                                      bf[cur][nj >> 1][(nj & 1) * 2 + 1]};
                    MMA16816(acc[mi][nj], af[cur][mi], bb);
                }
        }
    }

    // ---- epilogue: direct reg -> global with bias ----
    #pragma unroll
    for (int nj = 0; nj < 8; nj++) {
        int n = n0 + wn + nj * 8 + (lid & 3) * 2;
        float2 bv = *(const float2*)(bias + n);
        #pragma unroll
        for (int mi = 0; mi < 4; mi++) {
            int m = m0 + wm + mi * 16 + (lid >> 2);
            float2 v0 = {acc[mi][nj][0] + bv.x, acc[mi][nj][1] + bv.y};
            float2 v1 = {acc[mi][nj][2] + bv.x, acc[mi][nj][3] + bv.y};
            *(float2*)(out + (size_t)m * NDIM + n) = v0;
            *(float2*)(out + (size_t)(m + 8) * NDIM + n) = v1;
        }
    }
}

// ============================ launch ==================================
extern "C" void kernel_launch(void* const* d_in, const int* in_sizes, int n_in,
                              void* d_out, int out_size) {
    const float* x    = (const float*)d_in[0];
    const float* w    = (const float*)d_in[1];
    const float* bias = (const float*)d_in[2];
    float* out = (float*)d_out;

    absum_kernel<<<2048, 256>>>(w);
    gamma_kernel<<<1, 256>>>();
    quantconv_kernel<<<24576, 256>>>(w, x);

    cudaFuncSetAttribute(gemm_kernel, cudaFuncAttributeMaxDynamicSharedMemorySize,
                         SMEM_TOTAL);
    gemm_kernel<<<dim3(MDIM / BM, NDIM / BN), 256, SMEM_TOTAL>>>(out, bias);
}

// round 5
// speedup vs baseline: 1.1591x; 1.1290x over previous
#include <cuda_runtime.h>
#include <cuda_fp16.h>
#include <cstdint>
#include <cstddef>

// ============================ problem dims ============================
#define MDIM 8192
#define NDIM 4096
#define KDIM 4096

// ============================ scratch (no allocs allowed) =============
__device__ __half g_Xh[(size_t)MDIM * KDIM];   // 67 MB fp16 activations
__device__ __half g_Wh[(size_t)NDIM * KDIM];   // 34 MB fp16 ternary weights
__device__ double g_part[2048];
__device__ float  g_gamma;

// ============================ PTX helpers =============================
__device__ __forceinline__ uint32_t s2u(const void* p) {
    uint32_t a;
    asm("{ .reg .u64 t; cvta.to.shared.u64 t, %1; cvt.u32.u64 %0, t; }"
        : "=r"(a) : "l"(p));
    return a;
}

#define CP16(dst, src) \
    asm volatile("cp.async.cg.shared.global [%0], [%1], 16;" :: "r"(dst), "l"(src))
#define CP_COMMIT() asm volatile("cp.async.commit_group;" ::: "memory")
#define CP_WAIT(n)  asm volatile("cp.async.wait_group %0;" :: "n"(n) : "memory")

#define LDSM_X4(r0, r1, r2, r3, addr) \
    asm volatile("ldmatrix.sync.aligned.m8n8.x4.shared.b16 {%0,%1,%2,%3}, [%4];" \
                 : "=r"(r0), "=r"(r1), "=r"(r2), "=r"(r3) : "r"(addr))

#define MMA16816(c, a, b) \
    asm volatile("mma.sync.aligned.m16n8k16.row.col.f32.f16.f16.f32 " \
                 "{%0,%1,%2,%3}, {%4,%5,%6,%7}, {%8,%9}, {%0,%1,%2,%3};" \
                 : "+f"((c)[0]), "+f"((c)[1]), "+f"((c)[2]), "+f"((c)[3]) \
                 : "r"((a)[0]), "r"((a)[1]), "r"((a)[2]), "r"((a)[3]), \
                   "r"((b)[0]), "r"((b)[1]))

// ============================ prepass kernels =========================
__global__ void absum_kernel(const float* __restrict__ w) {
    __shared__ double sh[256];
    int tid = threadIdx.x;
    size_t idx = (size_t)blockIdx.x * 256 + tid;
    double s = 0.0;
    #pragma unroll 4
    for (int i = 0; i < 32; i++)
        s += (double)fabsf(w[idx + (size_t)i * 524288]);
    sh[tid] = s; __syncthreads();
    for (int off = 128; off; off >>= 1) {
        if (tid < off) sh[tid] += sh[tid + off];
        __syncthreads();
    }
    if (tid == 0) g_part[blockIdx.x] = sh[0];
}

__global__ void gamma_kernel() {
    __shared__ double sh[256];
    int tid = threadIdx.x;
    double s = 0.0;
    for (int i = 0; i < 8; i++) s += g_part[tid * 8 + i];
    sh[tid] = s; __syncthreads();
    for (int off = 128; off; off >>= 1) {
        if (tid < off) sh[tid] += sh[tid + off];
        __syncthreads();
    }
    if (tid == 0) {
        float gm = (float)(sh[0] / 16777216.0);
        g_gamma = fmaxf(gm, 1e-8f);
    }
}

// merged: blocks [0,8192) ternary-quantize W -> fp16; rest convert X -> fp16.
__global__ void quantconv_kernel(const float* __restrict__ w,
                                 const float* __restrict__ x) {
    size_t bid = blockIdx.x;
    if (bid < 8192) {
        float g = g_gamma;
        size_t base = (bid * 256 + threadIdx.x) * 8;
        float4 a = *(const float4*)(w + base);
        float4 b = *(const float4*)(w + base + 4);
        float v[8] = {a.x, a.y, a.z, a.w, b.x, b.y, b.z, b.w};
        __half h[8];
        #pragma unroll
        for (int i = 0; i < 8; i++) {
            float q = rintf(__fdiv_rn(v[i], g));   // round-half-even, IEEE div
            q = fminf(fmaxf(q, -1.0f), 1.0f);
            h[i] = __float2half_rn(q);
        }
        *(uint4*)(&g_Wh[base]) = *(const uint4*)h;
    } else {
        size_t base = ((bid - 8192) * 256 + threadIdx.x) * 8;
        float4 a = *(const float4*)(x + base);
        float4 b = *(const float4*)(x + base + 4);
        __half h[8] = {__float2half_rn(a.x), __float2half_rn(a.y),
                       __float2half_rn(a.z), __float2half_rn(a.w),
                       __float2half_rn(b.x), __float2half_rn(b.y),
                       __float2half_rn(b.z), __float2half_rn(b.w)};
        *(uint4*)(&g_Xh[base]) = *(const uint4*)h;
    }
}

// ============================ GEMM kernel =============================
// CTA 128(M) x 128(N), 128 thr = 4 warps (2x2), warp tile 64x64.
// 3-stage cp.async pipeline (96 KB SMEM) -> 2 CTAs per SM so barriers of
// one CTA overlap math of the other. Single-buffered fragments (reg budget).
#define BM 128
#define BN 128
#define KSTEP 64
#define NK (KDIM / KSTEP)                 // 64
#define STAGES 3
#define A_BYTES (BM * 128)                // 16 KB
#define B_BYTES (BN * 128)                // 16 KB
#define STG_BYTES (A_BYTES + B_BYTES)     // 32 KB
#define SMEM_TOTAL (STAGES * STG_BYTES)   // 96 KB

__global__ void __launch_bounds__(128, 2)
gemm_kernel(float* __restrict__ out, const float* __restrict__ bias) {
    extern __shared__ char smem[];
    uint32_t sb = s2u(smem);
    int tid = threadIdx.x, wid = tid >> 5, lid = tid & 31;
    int m0 = blockIdx.x * BM;
    int n0 = blockIdx.y * BN;
    int wm = (wid >> 1) * 64;
    int wn = (wid & 1) * 64;

    int a_row = wm + (lid & 15);
    int a_ks  = lid >> 4;
    int b_row = wn + ((lid >> 4) << 3) + (lid & 7);
    int b_ks  = (lid >> 3) & 1;

    float acc[4][8][4];
    #pragma unroll
    for (int i = 0; i < 4; i++)
        #pragma unroll
        for (int j = 0; j < 8; j++)
            #pragma unroll
            for (int r = 0; r < 4; r++) acc[i][j][r] = 0.0f;

    auto load_stage = [&](int buf, int kt) {
        int k0 = kt * KSTEP;
        uint32_t sA = sb + buf * STG_BYTES;
        uint32_t sB = sA + A_BYTES;
        #pragma unroll
        for (int i = 0; i < 8; i++) {              // A: 128 rows x 8 chunks
            int cid = tid + i * 128;
            int row = cid >> 3, ch = cid & 7;
            const __half* src = &g_Xh[(size_t)(m0 + row) * KDIM + k0 + ch * 8];
            CP16(sA + row * 128 + ((ch ^ (row & 7)) << 4), src);
        }
        #pragma unroll
        for (int i = 0; i < 8; i++) {              // B: 128 rows x 8 chunks
            int cid = tid + i * 128;
            int row = cid >> 3, ch = cid & 7;
            const __half* src = &g_Wh[(size_t)(n0 + row) * KDIM + k0 + ch * 8];
            CP16(sB + row * 128 + ((ch ^ (row & 7)) << 4), src);
        }
    };

    auto ldfrags = [&](int kchb, uint32_t sA, uint32_t sB,
                       uint32_t (&af)[4][4], uint32_t (&bf)[4][4]) {
        #pragma unroll
        for (int mi = 0; mi < 4; mi++) {
            int m = a_row + mi * 16;
            int kch = kchb + a_ks;
            uint32_t ad = sA + m * 128 + ((kch ^ (m & 7)) << 4);
            LDSM_X4(af[mi][0], af[mi][1], af[mi][2], af[mi][3], ad);
        }
        #pragma unroll
        for (int ni = 0; ni < 4; ni++) {
            int n = b_row + ni * 16;
            int kch = kchb + b_ks;
            uint32_t bd = sB + n * 128 + ((kch ^ (n & 7)) << 4);
            LDSM_X4(bf[ni][0], bf[ni][1], bf[ni][2], bf[ni][3], bd);
        }
    };

    #pragma unroll
    for (int s = 0; s < STAGES - 1; s++) { load_stage(s, s); CP_COMMIT(); }

    uint32_t af[4][4], bf[4][4];

    #pragma unroll 1
    for (int kt = 0; kt < NK; kt++) {
        CP_WAIT(STAGES - 2);
        __syncthreads();

        int buf = kt % STAGES;
        uint32_t sA = sb + buf * STG_BYTES;
        uint32_t sB = sA + A_BYTES;

        #pragma unroll
        for (int kk = 0; kk < 4; kk++) {
            ldfrags(kk * 2, sA, sB, af, bf);
            if (kk == 0) {
                // issue next stage's cp.asyncs; their cost hides LDSM latency
                int nk = kt + STAGES - 1;
                if (nk < NK) load_stage(nk % STAGES, nk);
                CP_COMMIT();
            }
            #pragma unroll
            for (int mi = 0; mi < 4; mi++)
                #pragma unroll
                for (int nj = 0; nj < 8; nj++) {
                    uint32_t bb[2] = {bf[nj >> 1][(nj & 1) * 2],
                                      bf[nj >> 1][(nj & 1) * 2 + 1]};
                    MMA16816(acc[mi][nj], af[mi], bb);
                }
        }
    }

    // ---- epilogue: direct reg -> global with bias ----
    #pragma unroll
    for (int nj = 0; nj < 8; nj++) {
        int n = n0 + wn + nj * 8 + (lid & 3) * 2;
        float2 bv = *(const float2*)(bias + n);
        #pragma unroll
        for (int mi = 0; mi < 4; mi++) {
            int m = m0 + wm + mi * 16 + (lid >> 2);
            float2 v0 = {acc[mi][nj][0] + bv.x, acc[mi][nj][1] + bv.y};
            float2 v1 = {acc[mi][nj][2] + bv.x, acc[mi][nj][3] + bv.y};
            *(float2*)(out + (size_t)m * NDIM + n) = v0;
            *(float2*)(out + (size_t)(m + 8) * NDIM + n) = v1;
        }
    }
}

// ============================ launch ==================================
extern "C" void kernel_launch(void* const* d_in, const int* in_sizes, int n_in,
                              void* d_out, int out_size) {
    const float* x    = (const float*)d_in[0];
    const float* w    = (const float*)d_in[1];
    const float* bias = (const float*)d_in[2];
    float* out = (float*)d_out;

    absum_kernel<<<2048, 256>>>(w);
    gamma_kernel<<<1, 256>>>();
    quantconv_kernel<<<24576, 256>>>(w, x);

    cudaFuncSetAttribute(gemm_kernel, cudaFuncAttributeMaxDynamicSharedMemorySize,
                         SMEM_TOTAL);
    gemm_kernel<<<dim3(MDIM / BM, NDIM / BN), 128, SMEM_TOTAL>>>(out, bias);
}